// round 14
// baseline (speedup 1.0000x reference)
#include <cuda_runtime.h>
#include <cuda_fp16.h>

#define NN   50000
#define EE   800000
#define IN_F 128
#define OUT_F 64
#define MAPF 64
#define NH   4
#define SCAN_BS 512
#define NB ((NN + SCAN_BS - 1) / SCAN_BS)   // 98

// ---------------- scratch (static device globals; no allocation) ----------------
__device__ int   g_count[NN];
__device__ int   g_off[NN + 1];
__device__ int   g_cursor[NN];
__device__ int   g_bsum[NB];
__device__ int   g_bbase[NB];
__device__ int   g_srcs[EE];
__device__ uint2    g_xh[NN * 32];    // x as fp16: 128 halfs/row
__device__ unsigned g_w1h[320 * 64];  // [W_gm | W_fc] K-major fp16: row n(0..319), 64 uints (128 k-halfs)
__device__ unsigned g_wmh[64 * 96];   // W_merge K-major fp16: row n(0..63), 96 uints (192 k-halfs)
__device__ unsigned g_zh[NN * 32];    // z as fp16: 64 halfs/row
__device__ uint2    g_fh[NN * 64];    // feat as fp16: 256 halfs/row ([h][64])
__device__ float4 g_eg[NN * 2];       // [2n] = el(4 heads), [2n+1] = gx3 = x@W_gate[192:320]
__device__ float4 g_er4[NN];          // er (4 heads)
__device__ float4 g_gx1[NN];          // x@W_gate[0:128]
__device__ uint2  g_gatedh[NN * 16];  // gated as fp16: 64 halfs/row

// ---------------- helpers ----------------
__device__ __forceinline__ void hmma16(float* c, unsigned a0, unsigned a1, unsigned a2,
                                       unsigned a3, unsigned b0, unsigned b1) {
    asm volatile(
        "mma.sync.aligned.m16n8k16.row.col.f32.f16.f16.f32 "
        "{%0,%1,%2,%3},{%4,%5,%6,%7},{%8,%9},{%0,%1,%2,%3};"
        : "+f"(c[0]), "+f"(c[1]), "+f"(c[2]), "+f"(c[3])
        : "r"(a0), "r"(a1), "r"(a2), "r"(a3), "r"(b0), "r"(b1));
}
__device__ __forceinline__ void ldsm4(unsigned& r0, unsigned& r1, unsigned& r2,
                                      unsigned& r3, unsigned saddr) {
    asm volatile("ldmatrix.sync.aligned.m8n8.x4.shared.b16 {%0,%1,%2,%3}, [%4];"
                 : "=r"(r0), "=r"(r1), "=r"(r2), "=r"(r3) : "r"(saddr));
}
__device__ __forceinline__ unsigned s2u(const void* p) {
    return (unsigned)__cvta_generic_to_shared(p);
}
__device__ __forceinline__ void cp16(unsigned dst, const void* src) {
    asm volatile("cp.async.cg.shared.global [%0], [%1], 16;" :: "r"(dst), "l"(src));
}
__device__ __forceinline__ void cp_commit() { asm volatile("cp.async.commit_group;"); }
__device__ __forceinline__ void cp_wait1()  { asm volatile("cp.async.wait_group 1;"); }
__device__ __forceinline__ void cp_wait0()  { asm volatile("cp.async.wait_group 0;"); }
__device__ __forceinline__ unsigned packh2(float a, float b) {
    __half2 h = __floats2half2_rn(a, b);
    return *(unsigned*)&h;
}
__device__ __forceinline__ float2 unpackh2(unsigned u) {
    return __half22float2(*(__half2*)&u);
}

// ---------------- CSR build ----------------
__global__ void k_zero() {
    int i = blockIdx.x * blockDim.x + threadIdx.x;
    if (i < NN) g_count[i] = 0;
}

__global__ void k_hist(const int* __restrict__ dst) {
    int e4 = blockIdx.x * blockDim.x + threadIdx.x;
    if (e4 < EE / 4) {
        int4 d = ((const int4*)dst)[e4];
        atomicAdd(&g_count[d.x], 1);
        atomicAdd(&g_count[d.y], 1);
        atomicAdd(&g_count[d.z], 1);
        atomicAdd(&g_count[d.w], 1);
    }
}

__global__ void k_scan1() {
    __shared__ int wsum[16];
    int b = blockIdx.x, t = threadIdx.x, lane = t & 31, w = t >> 5;
    int i = b * SCAN_BS + t;
    int v = (i < NN) ? g_count[i] : 0;
    int xs = v;
    #pragma unroll
    for (int d = 1; d < 32; d <<= 1) {
        int y = __shfl_up_sync(0xffffffffu, xs, d);
        if (lane >= d) xs += y;
    }
    if (lane == 31) wsum[w] = xs;
    __syncthreads();
    if (w == 0) {
        int s = (lane < 16) ? wsum[lane] : 0;
        #pragma unroll
        for (int d = 1; d < 16; d <<= 1) {
            int y = __shfl_up_sync(0xffffffffu, s, d);
            if (lane >= d) s += y;
        }
        if (lane < 16) wsum[lane] = s;
    }
    __syncthreads();
    int base = (w > 0) ? wsum[w - 1] : 0;
    if (i < NN) g_off[i] = base + xs - v;
    if (t == SCAN_BS - 1) g_bsum[b] = wsum[15];
}

__global__ void k_scan2() {
    __shared__ int ws[4];
    int t = threadIdx.x, lane = t & 31, w = t >> 5;
    int v = (t < NB) ? g_bsum[t] : 0;
    int xs = v;
    #pragma unroll
    for (int d = 1; d < 32; d <<= 1) {
        int y = __shfl_up_sync(0xffffffffu, xs, d);
        if (lane >= d) xs += y;
    }
    if (lane == 31) ws[w] = xs;
    __syncthreads();
    if (t == 0) {
        int a = 0;
        #pragma unroll
        for (int k = 0; k < 4; k++) { int tmp = ws[k]; ws[k] = a; a += tmp; }
    }
    __syncthreads();
    if (t < NB) g_bbase[t] = ws[w] + xs - v;
}

__global__ void k_scan3() {
    int b = blockIdx.x, t = threadIdx.x;
    int i = b * SCAN_BS + t;
    if (i < NN) {
        int o = g_off[i] + g_bbase[b];
        g_off[i] = o;
        g_cursor[i] = o;
    }
    if (i == 0) g_off[NN] = EE;
}

__global__ void k_scatter(const int* __restrict__ src, const int* __restrict__ dst) {
    int e4 = blockIdx.x * blockDim.x + threadIdx.x;
    if (e4 < EE / 4) {
        int4 d = ((const int4*)dst)[e4];
        int4 s = ((const int4*)src)[e4];
        g_srcs[atomicAdd(&g_cursor[d.x], 1)] = s.x;
        g_srcs[atomicAdd(&g_cursor[d.y], 1)] = s.y;
        g_srcs[atomicAdd(&g_cursor[d.z], 1)] = s.z;
        g_srcs[atomicAdd(&g_cursor[d.w], 1)] = s.w;
    }
}

// ---------------- fp16 prep ----------------
__global__ void k_xhalf(const float* __restrict__ x) {
    int i = blockIdx.x * blockDim.x + threadIdx.x;
    if (i < NN * 32) {
        float4 v = ((const float4*)x)[i];
        uint2 u;
        u.x = packh2(v.x, v.y);
        u.y = packh2(v.z, v.w);
        g_xh[i] = u;
    }
}

__global__ void k_wprep(const float* __restrict__ Wgm, const float* __restrict__ Wfc,
                        const float* __restrict__ Wm) {
    int i = blockIdx.x * blockDim.x + threadIdx.x;
    if (i < 320 * 64) {
        int n = i >> 6, j = i & 63;
        int k = 2 * j;
        float a, b;
        if (n < 64) { a = Wgm[k * 64 + n];        b = Wgm[(k + 1) * 64 + n]; }
        else        { a = Wfc[k * 256 + n - 64];  b = Wfc[(k + 1) * 256 + n - 64]; }
        g_w1h[i] = packh2(a, b);
    } else {
        int i2 = i - 320 * 64;
        if (i2 < 64 * 96) {
            int n = i2 / 96, j = i2 % 96;
            int k = 2 * j;
            g_wmh[i2] = packh2(Wm[k * 64 + n], Wm[(k + 1) * 64 + n]);
        }
    }
}

// ---------------- GEMM1: fp16 HMMA + ldmatrix + cp.async double buffer --------------
// smem layout identical to verified r13: rows 48B stride, k-tile slice in cols 0..7.
__global__ void k_gemm1(const float* __restrict__ bgm) {
    __shared__ unsigned Ah[2][128][12];
    __shared__ unsigned Bk[2][64][12];
    int t = threadIdx.x;
    int nt = blockIdx.y;
    int rowBase = blockIdx.x * 128;
    int lane = t & 31, wrp = t >> 5;
    int wm = wrp & 3, wn = wrp >> 2;

    float acc[2][4][4];
    #pragma unroll
    for (int mi = 0; mi < 2; mi++)
        #pragma unroll
        for (int ni = 0; ni < 4; ni++)
            #pragma unroll
            for (int q = 0; q < 4; q++) acc[mi][ni][q] = 0.f;

    // A copy: 256 threads, one 16B chunk each (row t>>1, half t&1)
    int arow = t >> 1, ahalf = t & 1;
    int grA = rowBase + arow; if (grA >= NN) grA = NN - 1;
    const uint2* asrc = &g_xh[grA * 32 + ahalf * 2];          // + kt*4 per tile
    unsigned adst = s2u(&Ah[0][arow][ahalf * 4]);
    // B copy: threads 0..127, one 16B chunk each (row (t>>1)&63)
    bool doB = t < 128;
    int brow = (t >> 1) & 63, bhalf = t & 1;
    const unsigned* bsrc = &g_w1h[(nt * 64 + brow) * 64 + bhalf * 4];  // + kt*8 per tile
    unsigned bdst = s2u(&Bk[0][brow][bhalf * 4]);

    // ldmatrix addresses
    int lrow = lane & 15, lhalf = lane >> 4;
    unsigned aAddr0 = s2u(&Ah[0][wm * 32 + lrow][lhalf * 4]);
    unsigned aAddr1 = s2u(&Ah[0][wm * 32 + 16 + lrow][lhalf * 4]);
    unsigned bAddr0 = s2u(&Bk[0][wn * 32 + lrow][lhalf * 4]);
    unsigned bAddr1 = s2u(&Bk[0][wn * 32 + 16 + lrow][lhalf * 4]);
    const unsigned ABUF = 128 * 12 * 4, BBUF = 64 * 12 * 4;

    // prologue: tile 0 -> buf 0
    cp16(adst, asrc);
    if (doB) cp16(bdst, bsrc);
    cp_commit();

    for (int kt = 0; kt < 8; kt++) {
        int cur = kt & 1;
        if (kt < 7) {
            int nxt = cur ^ 1;
            cp16(adst + nxt * ABUF, asrc + (kt + 1) * 4);
            if (doB) cp16(bdst + nxt * BBUF, bsrc + (kt + 1) * 8);
            cp_commit();
            cp_wait1();
        } else {
            cp_wait0();
        }
        __syncthreads();
        unsigned a[2][4], b[2][4];
        ldsm4(a[0][0], a[0][1], a[0][2], a[0][3], aAddr0 + cur * ABUF);
        ldsm4(a[1][0], a[1][1], a[1][2], a[1][3], aAddr1 + cur * ABUF);
        ldsm4(b[0][0], b[0][1], b[0][2], b[0][3], bAddr0 + cur * BBUF);
        ldsm4(b[1][0], b[1][1], b[1][2], b[1][3], bAddr1 + cur * BBUF);
        #pragma unroll
        for (int ni = 0; ni < 4; ni++) {
            unsigned b0 = b[ni >> 1][ni & 1];
            unsigned b1 = b[ni >> 1][(ni & 1) + 2];
            hmma16(acc[0][ni], a[0][0], a[0][1], a[0][2], a[0][3], b0, b1);
            hmma16(acc[1][ni], a[1][0], a[1][1], a[1][2], a[1][3], b0, b1);
        }
        __syncthreads();
    }

    int g = lane >> 2, tig = lane & 3;
    #pragma unroll
    for (int mi = 0; mi < 2; mi++) {
        #pragma unroll
        for (int ni = 0; ni < 4; ni++) {
            int lc = wn * 32 + ni * 8 + tig * 2;
            #pragma unroll
            for (int half = 0; half < 2; half++) {
                int r = rowBase + wm * 32 + mi * 16 + g + half * 8;
                if (r < NN) {
                    float v0 = acc[mi][ni][half * 2 + 0];
                    float v1 = acc[mi][ni][half * 2 + 1];
                    if (nt == 0) {
                        g_zh[r * 32 + (lc >> 1)] = packh2(v0 + bgm[lc], v1 + bgm[lc + 1]);
                    } else {
                        ((unsigned*)g_fh)[r * 128 + (((nt - 1) * 64 + lc) >> 1)] = packh2(v0, v1);
                    }
                }
            }
        }
    }
}

// ---------------- k_pre: el/er + gx1/gx3 per node (warp per node) ----------------
__global__ void k_pre(const float* __restrict__ x,
                      const float* __restrict__ al, const float* __restrict__ ar,
                      const float* __restrict__ Wg) {
    __shared__ float sW1[IN_F * NH];
    __shared__ float sW3[IN_F * NH];
    for (int i = threadIdx.x; i < IN_F * NH; i += blockDim.x) {
        sW1[i] = Wg[i];
        sW3[i] = Wg[192 * NH + i];
    }
    __syncthreads();
    int w = threadIdx.x >> 5, lane = threadIdx.x & 31;
    int n = blockIdx.x * 8 + w;
    if (n >= NN) return;
    int h1 = lane >> 4, q = lane & 15;

    uint2 ua = g_fh[n * 64 + lane];
    uint2 ub = g_fh[n * 64 + 32 + lane];
    float2 fa0 = unpackh2(ua.x), fa1 = unpackh2(ua.y);
    float2 fb0 = unpackh2(ub.x), fb1 = unpackh2(ub.y);
    const float4* al4 = (const float4*)al;
    const float4* ar4 = (const float4*)ar;
    float4 a0 = al4[h1 * 16 + q], a1 = al4[(h1 + 2) * 16 + q];
    float4 r0 = ar4[h1 * 16 + q], r1 = ar4[(h1 + 2) * 16 + q];
    float el0 = fa0.x * a0.x + fa0.y * a0.y + fa1.x * a0.z + fa1.y * a0.w;
    float el1 = fb0.x * a1.x + fb0.y * a1.y + fb1.x * a1.z + fb1.y * a1.w;
    float er0 = fa0.x * r0.x + fa0.y * r0.y + fa1.x * r0.z + fa1.y * r0.w;
    float er1 = fb0.x * r1.x + fb0.y * r1.y + fb1.x * r1.z + fb1.y * r1.w;

    float4 xv = ((const float4*)x)[n * 32 + lane];
    float gx1[4], gx3[4];
    int r = 4 * lane;
    #pragma unroll
    for (int h = 0; h < 4; h++) {
        gx1[h] = xv.x * sW1[(r + 0) * 4 + h] + xv.y * sW1[(r + 1) * 4 + h]
               + xv.z * sW1[(r + 2) * 4 + h] + xv.w * sW1[(r + 3) * 4 + h];
        gx3[h] = xv.x * sW3[(r + 0) * 4 + h] + xv.y * sW3[(r + 1) * 4 + h]
               + xv.z * sW3[(r + 2) * 4 + h] + xv.w * sW3[(r + 3) * 4 + h];
    }

    #pragma unroll
    for (int d = 8; d >= 1; d >>= 1) {
        el0 += __shfl_down_sync(0xffffffffu, el0, d);
        el1 += __shfl_down_sync(0xffffffffu, el1, d);
        er0 += __shfl_down_sync(0xffffffffu, er0, d);
        er1 += __shfl_down_sync(0xffffffffu, er1, d);
    }
    #pragma unroll
    for (int d = 16; d >= 1; d >>= 1) {
        #pragma unroll
        for (int h = 0; h < 4; h++) {
            gx1[h] += __shfl_xor_sync(0xffffffffu, gx1[h], d);
            gx3[h] += __shfl_xor_sync(0xffffffffu, gx3[h], d);
        }
    }
    float elh1 = __shfl_sync(0xffffffffu, el0, 16);
    float elh3 = __shfl_sync(0xffffffffu, el1, 16);
    float erh1 = __shfl_sync(0xffffffffu, er0, 16);
    float erh3 = __shfl_sync(0xffffffffu, er1, 16);
    if (lane == 0) {
        g_eg[2 * n]     = make_float4(el0, elh1, el1, elh3);
        g_eg[2 * n + 1] = make_float4(gx3[0], gx3[1], gx3[2], gx3[3]);
        g_er4[n]        = make_float4(er0, erh1, er1, erh3);
        g_gx1[n]        = make_float4(gx1[0], gx1[1], gx1[2], gx1[3]);
    }
}

// ---------------- fused single-pass agg (round-8 structure; fp16 gated store) ---------
__global__ void k_agg(const float* __restrict__ Wg, const float* __restrict__ bg,
                      const float* __restrict__ bgat) {
    __shared__ float sW2[MAPF * NH];
    for (int i = threadIdx.x; i < MAPF * NH; i += blockDim.x) sW2[i] = Wg[IN_F * NH + i];
    __syncthreads();
    int w = threadIdx.x >> 5, lane = threadIdx.x & 31;
    int d = blockIdx.x * 8 + w;
    if (d >= NN) return;
    int o0 = g_off[d], o1 = g_off[d + 1];
    int deg = o1 - o0;

    float4 er4 = g_er4[d];
    float4 gx1d = g_gx1[d];
    int h1 = lane >> 4, q = lane & 15;

    float zmx = -1e30f, zmy = -1e30f;
    float gxs0 = 0.f, gxs1 = 0.f, gxs2 = 0.f, gxs3 = 0.f;
    float den0 = 0.f, den1 = 0.f, den2 = 0.f, den3 = 0.f;
    float4 acc0 = {0.f, 0.f, 0.f, 0.f}, acc1 = {0.f, 0.f, 0.f, 0.f};

    int i = o0;
    if (deg >= 4) {
        int last = o1 - 1;
        int p0 = g_srcs[i], p1 = g_srcs[i + 1], p2 = g_srcs[i + 2], p3 = g_srcs[i + 3];
        for (; i + 3 < o1; i += 4) {
            int s[4] = {p0, p1, p2, p3};
            unsigned zu[4]; float4 ev[4], g3[4]; uint2 ua[4], ub[4];
            #pragma unroll
            for (int j = 0; j < 4; j++) {
                zu[j] = g_zh[s[j] * 32 + lane];
                ev[j] = g_eg[2 * s[j]];
                g3[j] = g_eg[2 * s[j] + 1];
                ua[j] = g_fh[s[j] * 64 + lane];
                ub[j] = g_fh[s[j] * 64 + 32 + lane];
            }
            int nb = i + 4;
            p0 = g_srcs[min(nb,     last)];
            p1 = g_srcs[min(nb + 1, last)];
            p2 = g_srcs[min(nb + 2, last)];
            p3 = g_srcs[min(nb + 3, last)];
            #pragma unroll
            for (int j = 0; j < 4; j++) {
                float2 zv = unpackh2(zu[j]);
                zmx = fmaxf(zmx, zv.x); zmy = fmaxf(zmy, zv.y);
                gxs0 += g3[j].x; gxs1 += g3[j].y; gxs2 += g3[j].z; gxs3 += g3[j].w;
                float e0 = ev[j].x + er4.x, e1 = ev[j].y + er4.y;
                float e2 = ev[j].z + er4.z, e3 = ev[j].w + er4.w;
                e0 = (e0 > 0.f) ? e0 : 0.2f * e0;
                e1 = (e1 > 0.f) ? e1 : 0.2f * e1;
                e2 = (e2 > 0.f) ? e2 : 0.2f * e2;
                e3 = (e3 > 0.f) ? e3 : 0.2f * e3;
                float w0 = __expf(e0), w1 = __expf(e1);
                float w2 = __expf(e2), w3 = __expf(e3);
                den0 += w0; den1 += w1; den2 += w2; den3 += w3;
                float2 fa0 = unpackh2(ua[j].x), fa1 = unpackh2(ua[j].y);
                float2 fb0 = unpackh2(ub[j].x), fb1 = unpackh2(ub[j].y);
                float wa = (h1 == 0) ? w0 : w1;
                float wb = (h1 == 0) ? w2 : w3;
                acc0.x += wa * fa0.x; acc0.y += wa * fa0.y; acc0.z += wa * fa1.x; acc0.w += wa * fa1.y;
                acc1.x += wb * fb0.x; acc1.y += wb * fb0.y; acc1.z += wb * fb1.x; acc1.w += wb * fb1.y;
            }
        }
    }
    for (; i < o1; i++) {
        int s0 = g_srcs[i];
        unsigned zu0 = g_zh[s0 * 32 + lane];
        float4 ev0 = g_eg[2 * s0];
        float4 g30 = g_eg[2 * s0 + 1];
        uint2 ua0 = g_fh[s0 * 64 + lane];
        uint2 ub0 = g_fh[s0 * 64 + 32 + lane];
        float2 zv = unpackh2(zu0);
        zmx = fmaxf(zmx, zv.x); zmy = fmaxf(zmy, zv.y);
        gxs0 += g30.x; gxs1 += g30.y; gxs2 += g30.z; gxs3 += g30.w;
        float e0 = ev0.x + er4.x, e1 = ev0.y + er4.y;
        float e2 = ev0.z + er4.z, e3 = ev0.w + er4.w;
        e0 = (e0 > 0.f) ? e0 : 0.2f * e0;
        e1 = (e1 > 0.f) ? e1 : 0.2f * e1;
        e2 = (e2 > 0.f) ? e2 : 0.2f * e2;
        e3 = (e3 > 0.f) ? e3 : 0.2f * e3;
        float w0 = __expf(e0), w1 = __expf(e1);
        float w2 = __expf(e2), w3 = __expf(e3);
        den0 += w0; den1 += w1; den2 += w2; den3 += w3;
        float2 fa0 = unpackh2(ua0.x), fa1 = unpackh2(ua0.y);
        float2 fb0 = unpackh2(ub0.x), fb1 = unpackh2(ub0.y);
        float wa = (h1 == 0) ? w0 : w1;
        float wb = (h1 == 0) ? w2 : w3;
        acc0.x += wa * fa0.x; acc0.y += wa * fa0.y; acc0.z += wa * fa1.x; acc0.w += wa * fa1.y;
        acc1.x += wb * fb0.x; acc1.y += wb * fb0.y; acc1.z += wb * fb1.x; acc1.w += wb * fb1.y;
    }

    // ---- gate ----
    float inv = (deg > 0) ? 1.0f / (float)deg : 0.0f;
    if (deg == 0) { zmx = 0.f; zmy = 0.f; }
    float zr[4];
    int r2 = 2 * lane;
    #pragma unroll
    for (int h = 0; h < 4; h++)
        zr[h] = zmx * sW2[(r2 + 0) * 4 + h] + zmy * sW2[(r2 + 1) * 4 + h];
    #pragma unroll
    for (int dd = 16; dd >= 1; dd >>= 1) {
        #pragma unroll
        for (int h = 0; h < 4; h++) zr[h] += __shfl_xor_sync(0xffffffffu, zr[h], dd);
    }
    float gxs[4] = {gxs0, gxs1, gxs2, gxs3};
    float gx1a[4] = {gx1d.x, gx1d.y, gx1d.z, gx1d.w};
    float gate[4];
    #pragma unroll
    for (int h = 0; h < 4; h++) {
        float p = gx1a[h] + gxs[h] * inv + zr[h] + bg[h];
        gate[h] = 1.f / (1.f + __expf(-p));
    }

    // ---- normalize, bias, gate, head-average, store (fp16) ----
    float4 bga = ((const float4*)bgat)[h1 * 16 + q];
    float4 bgb = ((const float4*)bgat)[(h1 + 2) * 16 + q];
    float4 a0, a1;
    if (deg > 0) {
        float ia = 1.f / ((h1 == 0) ? den0 : den1);
        float ib = 1.f / ((h1 == 0) ? den2 : den3);
        a0.x = acc0.x * ia + bga.x; a0.y = acc0.y * ia + bga.y;
        a0.z = acc0.z * ia + bga.z; a0.w = acc0.w * ia + bga.w;
        a1.x = acc1.x * ib + bgb.x; a1.y = acc1.y * ib + bgb.y;
        a1.z = acc1.z * ib + bgb.z; a1.w = acc1.w * ib + bgb.w;
    } else {
        a0 = bga; a1 = bgb;
    }
    float g0 = (h1 == 0) ? gate[0] : gate[1];
    float g1 = (h1 == 0) ? gate[2] : gate[3];
    float4 pp;
    pp.x = g0 * a0.x + g1 * a1.x;
    pp.y = g0 * a0.y + g1 * a1.y;
    pp.z = g0 * a0.z + g1 * a1.z;
    pp.w = g0 * a0.w + g1 * a1.w;
    pp.x += __shfl_xor_sync(0xffffffffu, pp.x, 16);
    pp.y += __shfl_xor_sync(0xffffffffu, pp.y, 16);
    pp.z += __shfl_xor_sync(0xffffffffu, pp.z, 16);
    pp.w += __shfl_xor_sync(0xffffffffu, pp.w, 16);
    pp.x *= 0.25f; pp.y *= 0.25f; pp.z *= 0.25f; pp.w *= 0.25f;
    if (lane < 16) {
        uint2 u;
        u.x = packh2(pp.x, pp.y);
        u.y = packh2(pp.z, pp.w);
        g_gatedh[d * 16 + lane] = u;
    }
}

// ---------------- merge GEMM: fp16 HMMA + ldmatrix + cp.async double buffer ----------
__global__ void k_merge(const float* __restrict__ bm, float* __restrict__ out) {
    __shared__ unsigned Ah[2][128][12];
    __shared__ unsigned Bk[2][64][12];
    int t = threadIdx.x;
    int rowBase = blockIdx.x * 128;
    int lane = t & 31, wrp = t >> 5;
    int wm = wrp & 3, wn = wrp >> 2;

    float acc[2][4][4];
    #pragma unroll
    for (int mi = 0; mi < 2; mi++)
        #pragma unroll
        for (int ni = 0; ni < 4; ni++)
            #pragma unroll
            for (int q = 0; q < 4; q++) acc[mi][ni][q] = 0.f;

    int arow = t >> 1, ahalf = t & 1;
    int grA = rowBase + arow; if (grA >= NN) grA = NN - 1;
    const uint2* axsrc = &g_xh[grA * 32 + ahalf * 2];       // + kt*4 (kt<8)
    const uint2* agsrc = &g_gatedh[grA * 16 + ahalf * 2];   // + (kt-8)*4 (kt>=8)
    unsigned adst = s2u(&Ah[0][arow][ahalf * 4]);
    bool doB = t < 128;
    int brow = (t >> 1) & 63, bhalf = t & 1;
    const unsigned* bsrc = &g_wmh[brow * 96 + bhalf * 4];   // + kt*8
    unsigned bdst = s2u(&Bk[0][brow][bhalf * 4]);

    int lrow = lane & 15, lhalf = lane >> 4;
    unsigned aAddr0 = s2u(&Ah[0][wm * 32 + lrow][lhalf * 4]);
    unsigned aAddr1 = s2u(&Ah[0][wm * 32 + 16 + lrow][lhalf * 4]);
    unsigned bAddr0 = s2u(&Bk[0][wn * 32 + lrow][lhalf * 4]);
    unsigned bAddr1 = s2u(&Bk[0][wn * 32 + 16 + lrow][lhalf * 4]);
    const unsigned ABUF = 128 * 12 * 4, BBUF = 64 * 12 * 4;

    // tile 0
    cp16(adst, axsrc);
    if (doB) cp16(bdst, bsrc);
    cp_commit();

    for (int kt = 0; kt < 12; kt++) {
        int cur = kt & 1;
        if (kt < 11) {
            int nxt = cur ^ 1;
            int kn = kt + 1;
            const void* asrcN = (kn < 8) ? (const void*)(axsrc + kn * 4)
                                         : (const void*)(agsrc + (kn - 8) * 4);
            cp16(adst + nxt * ABUF, asrcN);
            if (doB) cp16(bdst + nxt * BBUF, bsrc + kn * 8);
            cp_commit();
            cp_wait1();
        } else {
            cp_wait0();
        }
        __syncthreads();
        unsigned a[2][4], b[2][4];
        ldsm4(a[0][0], a[0][1], a[0][2], a[0][3], aAddr0 + cur * ABUF);
        ldsm4(a[1][0], a[1][1], a[1][2], a[1][3], aAddr1 + cur * ABUF);
        ldsm4(b[0][0], b[0][1], b[0][2], b[0][3], bAddr0 + cur * BBUF);
        ldsm4(b[1][0], b[1][1], b[1][2], b[1][3], bAddr1 + cur * BBUF);
        #pragma unroll
        for (int ni = 0; ni < 4; ni++) {
            unsigned b0 = b[ni >> 1][ni & 1];
            unsigned b1 = b[ni >> 1][(ni & 1) + 2];
            hmma16(acc[0][ni], a[0][0], a[0][1], a[0][2], a[0][3], b0, b1);
            hmma16(acc[1][ni], a[1][0], a[1][1], a[1][2], a[1][3], b0, b1);
        }
        __syncthreads();
    }

    int g = lane >> 2, tig = lane & 3;
    #pragma unroll
    for (int mi = 0; mi < 2; mi++) {
        #pragma unroll
        for (int ni = 0; ni < 4; ni++) {
            int lc = wn * 32 + ni * 8 + tig * 2;
            #pragma unroll
            for (int half = 0; half < 2; half++) {
                int r = rowBase + wm * 32 + mi * 16 + g + half * 8;
                if (r < NN) {
                    out[r * OUT_F + lc]     = acc[mi][ni][half * 2 + 0] + bm[lc];
                    out[r * OUT_F + lc + 1] = acc[mi][ni][half * 2 + 1] + bm[lc + 1];
                }
            }
        }
    }
}

// ---------------- launch ----------------
extern "C" void kernel_launch(void* const* d_in, const int* in_sizes, int n_in,
                              void* d_out, int out_size) {
    const float* x      = (const float*)d_in[0];
    const int*   ei     = (const int*)d_in[1];
    const float* W_gm   = (const float*)d_in[2];
    const float* b_gm   = (const float*)d_in[3];
    const float* W_gate = (const float*)d_in[4];
    const float* b_gate = (const float*)d_in[5];
    const float* W_fc   = (const float*)d_in[6];
    const float* attn_l = (const float*)d_in[7];
    const float* attn_r = (const float*)d_in[8];
    const float* b_gat  = (const float*)d_in[9];
    const float* W_mrg  = (const float*)d_in[10];
    const float* b_mrg  = (const float*)d_in[11];
    float* out = (float*)d_out;

    const int* src = ei;
    const int* dst = ei + EE;

    k_zero<<<(NN + 255) / 256, 256>>>();
    k_xhalf<<<(NN * 32 + 255) / 256, 256>>>(x);
    k_wprep<<<(320 * 64 + 64 * 96 + 255) / 256, 256>>>(W_gm, W_fc, W_mrg);
    k_gemm1<<<dim3((NN + 127) / 128, 5), 256>>>(b_gm);   // index 3: profiled
    k_hist<<<(EE / 4 + 255) / 256, 256>>>(dst);
    k_scan1<<<NB, SCAN_BS>>>();
    k_scan2<<<1, 128>>>();
    k_scan3<<<NB, SCAN_BS>>>();
    k_scatter<<<(EE / 4 + 255) / 256, 256>>>(src, dst);
    k_pre<<<(NN + 7) / 8, 256>>>(x, attn_l, attn_r, W_gate);
    k_agg<<<(NN + 7) / 8, 256>>>(W_gate, b_gate, b_gat);
    k_merge<<<(NN + 127) / 128, 256>>>(b_mrg, out);
}

// round 16
// speedup vs baseline: 1.0597x; 1.0597x over previous
#include <cuda_runtime.h>
#include <cuda_fp16.h>

#define NN   50000
#define EE   800000
#define IN_F 128
#define OUT_F 64
#define MAPF 64
#define NH   4
#define SCAN_BS 512
#define NB ((NN + SCAN_BS - 1) / SCAN_BS)   // 98

// ---------------- scratch (static device globals; no allocation) ----------------
__device__ int   g_count[NN];
__device__ int   g_off[NN + 1];
__device__ int   g_cursor[NN];
__device__ int   g_bsum[NB];
__device__ int   g_bbase[NB];
__device__ int   g_srcs[EE];
__device__ uint2    g_xh[NN * 32];    // x as fp16: 128 halfs/row
__device__ unsigned g_w1h[320 * 64];  // [W_gm | W_fc] K-major fp16
__device__ unsigned g_wmh[64 * 96];   // W_merge K-major fp16
__device__ unsigned g_zh[NN * 32];    // z as fp16
__device__ uint2    g_fh[NN * 64];    // feat as fp16 ([h][64])
__device__ float4 g_eg[NN * 2];       // [2n]=el, [2n+1]=gx3
__device__ float4 g_er4[NN];
__device__ float4 g_gx1[NN];
__device__ uint2  g_gatedh[NN * 16];  // gated as fp16

// ---------------- helpers ----------------
__device__ __forceinline__ void hmma16(float* c, unsigned a0, unsigned a1, unsigned a2,
                                       unsigned a3, unsigned b0, unsigned b1) {
    asm volatile(
        "mma.sync.aligned.m16n8k16.row.col.f32.f16.f16.f32 "
        "{%0,%1,%2,%3},{%4,%5,%6,%7},{%8,%9},{%0,%1,%2,%3};"
        : "+f"(c[0]), "+f"(c[1]), "+f"(c[2]), "+f"(c[3])
        : "r"(a0), "r"(a1), "r"(a2), "r"(a3), "r"(b0), "r"(b1));
}
__device__ __forceinline__ void ldsm4(unsigned& r0, unsigned& r1, unsigned& r2,
                                      unsigned& r3, unsigned saddr) {
    asm volatile("ldmatrix.sync.aligned.m8n8.x4.shared.b16 {%0,%1,%2,%3}, [%4];"
                 : "=r"(r0), "=r"(r1), "=r"(r2), "=r"(r3) : "r"(saddr));
}
__device__ __forceinline__ unsigned s2u(const void* p) {
    return (unsigned)__cvta_generic_to_shared(p);
}
__device__ __forceinline__ void cp16(unsigned dst, const void* src) {
    asm volatile("cp.async.cg.shared.global [%0], [%1], 16;" :: "r"(dst), "l"(src));
}
__device__ __forceinline__ void cp_commit() { asm volatile("cp.async.commit_group;"); }
__device__ __forceinline__ void cp_wait0()  { asm volatile("cp.async.wait_group 0;"); }
__device__ __forceinline__ void cp_wait1()  { asm volatile("cp.async.wait_group 1;"); }
__device__ __forceinline__ unsigned packh2(float a, float b) {
    __half2 h = __floats2half2_rn(a, b);
    return *(unsigned*)&h;
}
__device__ __forceinline__ float2 unpackh2(unsigned u) {
    return __half22float2(*(__half2*)&u);
}

// ---------------- fused: zero counts + x->fp16 + weights->fp16 + histogram ----------
__global__ void k_histprep(const float* __restrict__ x,
                           const float* __restrict__ Wgm, const float* __restrict__ Wfc,
                           const float* __restrict__ Wm, const int* __restrict__ dst) {
    int i = blockIdx.x * blockDim.x + threadIdx.x;
    if (i < NN) g_count[i] = 0;
    if (i < NN * 32) {
        float4 v = ((const float4*)x)[i];
        uint2 u;
        u.x = packh2(v.x, v.y);
        u.y = packh2(v.z, v.w);
        g_xh[i] = u;
    }
    if (i < 320 * 64) {
        int n = i >> 6, j = i & 63;
        int k = 2 * j;
        float a, b;
        if (n < 64) { a = Wgm[k * 64 + n];        b = Wgm[(k + 1) * 64 + n]; }
        else        { a = Wfc[k * 256 + n - 64];  b = Wfc[(k + 1) * 256 + n - 64]; }
        g_w1h[i] = packh2(a, b);
    } else {
        int i2 = i - 320 * 64;
        if (i2 < 64 * 96) {
            int n = i2 / 96, j = i2 % 96;
            int k = 2 * j;
            g_wmh[i2] = packh2(Wm[k * 64 + n], Wm[(k + 1) * 64 + n]);
        }
    }
    // histogram must run after ALL zeroing; different blocks race on g_count.
    // Safe because zeroing for index i happens in thread i, and histogram uses
    // atomicAdd on arbitrary indices -> needs completed zero. To avoid the race,
    // histogram is placed in its own kernel below. (This kernel only preps.)
}

__global__ void k_hist(const int* __restrict__ dst) {
    int e4 = blockIdx.x * blockDim.x + threadIdx.x;
    if (e4 < EE / 4) {
        int4 d = ((const int4*)dst)[e4];
        atomicAdd(&g_count[d.x], 1);
        atomicAdd(&g_count[d.y], 1);
        atomicAdd(&g_count[d.z], 1);
        atomicAdd(&g_count[d.w], 1);
    }
}

__global__ void k_scan1() {
    __shared__ int wsum[16];
    int b = blockIdx.x, t = threadIdx.x, lane = t & 31, w = t >> 5;
    int i = b * SCAN_BS + t;
    int v = (i < NN) ? g_count[i] : 0;
    int xs = v;
    #pragma unroll
    for (int d = 1; d < 32; d <<= 1) {
        int y = __shfl_up_sync(0xffffffffu, xs, d);
        if (lane >= d) xs += y;
    }
    if (lane == 31) wsum[w] = xs;
    __syncthreads();
    if (w == 0) {
        int s = (lane < 16) ? wsum[lane] : 0;
        #pragma unroll
        for (int d = 1; d < 16; d <<= 1) {
            int y = __shfl_up_sync(0xffffffffu, s, d);
            if (lane >= d) s += y;
        }
        if (lane < 16) wsum[lane] = s;
    }
    __syncthreads();
    int base = (w > 0) ? wsum[w - 1] : 0;
    if (i < NN) g_off[i] = base + xs - v;
    if (t == SCAN_BS - 1) g_bsum[b] = wsum[15];
}

__global__ void k_scan2() {
    __shared__ int ws[4];
    int t = threadIdx.x, lane = t & 31, w = t >> 5;
    int v = (t < NB) ? g_bsum[t] : 0;
    int xs = v;
    #pragma unroll
    for (int d = 1; d < 32; d <<= 1) {
        int y = __shfl_up_sync(0xffffffffu, xs, d);
        if (lane >= d) xs += y;
    }
    if (lane == 31) ws[w] = xs;
    __syncthreads();
    if (t == 0) {
        int a = 0;
        #pragma unroll
        for (int k = 0; k < 4; k++) { int tmp = ws[k]; ws[k] = a; a += tmp; }
    }
    __syncthreads();
    if (t < NB) g_bbase[t] = ws[w] + xs - v;
}

__global__ void k_scan3() {
    int b = blockIdx.x, t = threadIdx.x;
    int i = b * SCAN_BS + t;
    if (i < NN) {
        int o = g_off[i] + g_bbase[b];
        g_off[i] = o;
        g_cursor[i] = o;
    }
    if (i == 0) g_off[NN] = EE;
}

__global__ void k_scatter(const int* __restrict__ src, const int* __restrict__ dst) {
    int e4 = blockIdx.x * blockDim.x + threadIdx.x;
    if (e4 < EE / 4) {
        int4 d = ((const int4*)dst)[e4];
        int4 s = ((const int4*)src)[e4];
        g_srcs[atomicAdd(&g_cursor[d.x], 1)] = s.x;
        g_srcs[atomicAdd(&g_cursor[d.y], 1)] = s.y;
        g_srcs[atomicAdd(&g_cursor[d.z], 1)] = s.z;
        g_srcs[atomicAdd(&g_cursor[d.w], 1)] = s.w;
    }
}

// ---------------- GEMM1: A-resident (XOR-swizzled 48KB smem), 5 output tiles ---------
// As: 128 rows x 64 words; Bs: 64 rows x 64 words. Chunk swizzle: q' = q ^ (row&7).
__global__ void k_gemm1(const float* __restrict__ bgm) {
    __shared__ unsigned As[128 * 64];   // 32 KB
    __shared__ unsigned Bs[64 * 64];    // 16 KB  (total 48 KB)
    int t = threadIdx.x;
    int rowBase = blockIdx.x * 128;
    int lane = t & 31, wrp = t >> 5;
    int wm = wrp & 3, wn = wrp >> 2;

    // A: 2048 16B chunks, 8 per thread (swizzled store)
    #pragma unroll
    for (int c = 0; c < 8; c++) {
        int ch = t + c * 256;
        int row = ch >> 4, q = ch & 15;
        int gr = rowBase + row; if (gr >= NN) gr = NN - 1;
        cp16(s2u(&As[row * 64 + ((q ^ (row & 7)) << 2)]), &g_xh[gr * 32 + q * 2]);
    }
    // B tile nt=0: 1024 chunks, 4 per thread
    #pragma unroll
    for (int c = 0; c < 4; c++) {
        int ch = t + c * 256;
        int row = ch >> 4, q = ch & 15;
        cp16(s2u(&Bs[row * 64 + ((q ^ (row & 7)) << 2)]), &g_w1h[row * 64 + q * 4]);
    }
    cp_commit();
    cp_wait0();
    __syncthreads();

    int lrow = lane & 15, lhalf = lane >> 4;
    int arw0 = wm * 32 + lrow, arw1 = arw0 + 16;   // (arw0&7)==(arw1&7)
    int brw0 = wn * 32 + lrow, brw1 = brw0 + 16;
    unsigned aB0 = s2u(As) + arw0 * 256;
    unsigned aB1 = s2u(As) + arw1 * 256;
    unsigned bB0 = s2u(Bs) + brw0 * 256;
    unsigned bB1 = s2u(Bs) + brw1 * 256;
    int ax = arw0 & 7, bx = brw0 & 7;
    int g = lane >> 2, tig = lane & 3;

    for (int nt = 0; nt < 5; nt++) {
        float acc[2][4][4];
        #pragma unroll
        for (int mi = 0; mi < 2; mi++)
            #pragma unroll
            for (int ni = 0; ni < 4; ni++)
                #pragma unroll
                for (int q = 0; q < 4; q++) acc[mi][ni][q] = 0.f;

        #pragma unroll
        for (int kt = 0; kt < 8; kt++) {
            int K = kt * 2 + lhalf;
            unsigned a[2][4], b[2][4];
            ldsm4(a[0][0], a[0][1], a[0][2], a[0][3], aB0 + ((K ^ ax) << 4));
            ldsm4(a[1][0], a[1][1], a[1][2], a[1][3], aB1 + ((K ^ ax) << 4));
            ldsm4(b[0][0], b[0][1], b[0][2], b[0][3], bB0 + ((K ^ bx) << 4));
            ldsm4(b[1][0], b[1][1], b[1][2], b[1][3], bB1 + ((K ^ bx) << 4));
            #pragma unroll
            for (int ni = 0; ni < 4; ni++) {
                unsigned b0 = b[ni >> 1][ni & 1];
                unsigned b1 = b[ni >> 1][(ni & 1) + 2];
                hmma16(acc[0][ni], a[0][0], a[0][1], a[0][2], a[0][3], b0, b1);
                hmma16(acc[1][ni], a[1][0], a[1][1], a[1][2], a[1][3], b0, b1);
            }
        }

        // epilogue (regs only; overlaps nothing in smem)
        #pragma unroll
        for (int mi = 0; mi < 2; mi++) {
            #pragma unroll
            for (int ni = 0; ni < 4; ni++) {
                int lc = wn * 32 + ni * 8 + tig * 2;
                #pragma unroll
                for (int half = 0; half < 2; half++) {
                    int r = rowBase + wm * 32 + mi * 16 + g + half * 8;
                    if (r < NN) {
                        float v0 = acc[mi][ni][half * 2 + 0];
                        float v1 = acc[mi][ni][half * 2 + 1];
                        if (nt == 0) {
                            g_zh[r * 32 + (lc >> 1)] = packh2(v0 + bgm[lc], v1 + bgm[lc + 1]);
                        } else {
                            ((unsigned*)g_fh)[r * 128 + (((nt - 1) * 64 + lc) >> 1)] = packh2(v0, v1);
                        }
                    }
                }
            }
        }
        if (nt < 4) {
            __syncthreads();   // everyone done reading Bs
            #pragma unroll
            for (int c = 0; c < 4; c++) {
                int ch = t + c * 256;
                int row = ch >> 4, q = ch & 15;
                cp16(s2u(&Bs[row * 64 + ((q ^ (row & 7)) << 2)]),
                     &g_w1h[((nt + 1) * 64 + row) * 64 + q * 4]);
            }
            cp_commit();
            cp_wait0();
            __syncthreads();
        }
    }
}

// ---------------- k_pre: el/er + gx1/gx3 per node (warp per node) ----------------
__global__ void k_pre(const float* __restrict__ x,
                      const float* __restrict__ al, const float* __restrict__ ar,
                      const float* __restrict__ Wg) {
    __shared__ float sW1[IN_F * NH];
    __shared__ float sW3[IN_F * NH];
    for (int i = threadIdx.x; i < IN_F * NH; i += blockDim.x) {
        sW1[i] = Wg[i];
        sW3[i] = Wg[192 * NH + i];
    }
    __syncthreads();
    int w = threadIdx.x >> 5, lane = threadIdx.x & 31;
    int n = blockIdx.x * 8 + w;
    if (n >= NN) return;
    int h1 = lane >> 4, q = lane & 15;

    uint2 ua = g_fh[n * 64 + lane];
    uint2 ub = g_fh[n * 64 + 32 + lane];
    float2 fa0 = unpackh2(ua.x), fa1 = unpackh2(ua.y);
    float2 fb0 = unpackh2(ub.x), fb1 = unpackh2(ub.y);
    const float4* al4 = (const float4*)al;
    const float4* ar4 = (const float4*)ar;
    float4 a0 = al4[h1 * 16 + q], a1 = al4[(h1 + 2) * 16 + q];
    float4 r0 = ar4[h1 * 16 + q], r1 = ar4[(h1 + 2) * 16 + q];
    float el0 = fa0.x * a0.x + fa0.y * a0.y + fa1.x * a0.z + fa1.y * a0.w;
    float el1 = fb0.x * a1.x + fb0.y * a1.y + fb1.x * a1.z + fb1.y * a1.w;
    float er0 = fa0.x * r0.x + fa0.y * r0.y + fa1.x * r0.z + fa1.y * r0.w;
    float er1 = fb0.x * r1.x + fb0.y * r1.y + fb1.x * r1.z + fb1.y * r1.w;

    float4 xv = ((const float4*)x)[n * 32 + lane];
    float gx1[4], gx3[4];
    int r = 4 * lane;
    #pragma unroll
    for (int h = 0; h < 4; h++) {
        gx1[h] = xv.x * sW1[(r + 0) * 4 + h] + xv.y * sW1[(r + 1) * 4 + h]
               + xv.z * sW1[(r + 2) * 4 + h] + xv.w * sW1[(r + 3) * 4 + h];
        gx3[h] = xv.x * sW3[(r + 0) * 4 + h] + xv.y * sW3[(r + 1) * 4 + h]
               + xv.z * sW3[(r + 2) * 4 + h] + xv.w * sW3[(r + 3) * 4 + h];
    }

    #pragma unroll
    for (int d = 8; d >= 1; d >>= 1) {
        el0 += __shfl_down_sync(0xffffffffu, el0, d);
        el1 += __shfl_down_sync(0xffffffffu, el1, d);
        er0 += __shfl_down_sync(0xffffffffu, er0, d);
        er1 += __shfl_down_sync(0xffffffffu, er1, d);
    }
    #pragma unroll
    for (int d = 16; d >= 1; d >>= 1) {
        #pragma unroll
        for (int h = 0; h < 4; h++) {
            gx1[h] += __shfl_xor_sync(0xffffffffu, gx1[h], d);
            gx3[h] += __shfl_xor_sync(0xffffffffu, gx3[h], d);
        }
    }
    float elh1 = __shfl_sync(0xffffffffu, el0, 16);
    float elh3 = __shfl_sync(0xffffffffu, el1, 16);
    float erh1 = __shfl_sync(0xffffffffu, er0, 16);
    float erh3 = __shfl_sync(0xffffffffu, er1, 16);
    if (lane == 0) {
        g_eg[2 * n]     = make_float4(el0, elh1, el1, elh3);
        g_eg[2 * n + 1] = make_float4(gx3[0], gx3[1], gx3[2], gx3[3]);
        g_er4[n]        = make_float4(er0, erh1, er1, erh3);
        g_gx1[n]        = make_float4(gx1[0], gx1[1], gx1[2], gx1[3]);
    }
}

// ---------------- fused single-pass agg (fp16 gated store) ----------------------------
__global__ void k_agg(const float* __restrict__ Wg, const float* __restrict__ bg,
                      const float* __restrict__ bgat) {
    __shared__ float sW2[MAPF * NH];
    for (int i = threadIdx.x; i < MAPF * NH; i += blockDim.x) sW2[i] = Wg[IN_F * NH + i];
    __syncthreads();
    int w = threadIdx.x >> 5, lane = threadIdx.x & 31;
    int d = blockIdx.x * 8 + w;
    if (d >= NN) return;
    int o0 = g_off[d], o1 = g_off[d + 1];
    int deg = o1 - o0;

    float4 er4 = g_er4[d];
    float4 gx1d = g_gx1[d];
    int h1 = lane >> 4, q = lane & 15;

    float zmx = -1e30f, zmy = -1e30f;
    float gxs0 = 0.f, gxs1 = 0.f, gxs2 = 0.f, gxs3 = 0.f;
    float den0 = 0.f, den1 = 0.f, den2 = 0.f, den3 = 0.f;
    float4 acc0 = {0.f, 0.f, 0.f, 0.f}, acc1 = {0.f, 0.f, 0.f, 0.f};

    int i = o0;
    if (deg >= 4) {
        int last = o1 - 1;
        int p0 = g_srcs[i], p1 = g_srcs[i + 1], p2 = g_srcs[i + 2], p3 = g_srcs[i + 3];
        for (; i + 3 < o1; i += 4) {
            int s[4] = {p0, p1, p2, p3};
            unsigned zu[4]; float4 ev[4], g3[4]; uint2 ua[4], ub[4];
            #pragma unroll
            for (int j = 0; j < 4; j++) {
                zu[j] = g_zh[s[j] * 32 + lane];
                ev[j] = g_eg[2 * s[j]];
                g3[j] = g_eg[2 * s[j] + 1];
                ua[j] = g_fh[s[j] * 64 + lane];
                ub[j] = g_fh[s[j] * 64 + 32 + lane];
            }
            int nb = i + 4;
            p0 = g_srcs[min(nb,     last)];
            p1 = g_srcs[min(nb + 1, last)];
            p2 = g_srcs[min(nb + 2, last)];
            p3 = g_srcs[min(nb + 3, last)];
            #pragma unroll
            for (int j = 0; j < 4; j++) {
                float2 zv = unpackh2(zu[j]);
                zmx = fmaxf(zmx, zv.x); zmy = fmaxf(zmy, zv.y);
                gxs0 += g3[j].x; gxs1 += g3[j].y; gxs2 += g3[j].z; gxs3 += g3[j].w;
                float e0 = ev[j].x + er4.x, e1 = ev[j].y + er4.y;
                float e2 = ev[j].z + er4.z, e3 = ev[j].w + er4.w;
                e0 = (e0 > 0.f) ? e0 : 0.2f * e0;
                e1 = (e1 > 0.f) ? e1 : 0.2f * e1;
                e2 = (e2 > 0.f) ? e2 : 0.2f * e2;
                e3 = (e3 > 0.f) ? e3 : 0.2f * e3;
                float w0 = __expf(e0), w1 = __expf(e1);
                float w2 = __expf(e2), w3 = __expf(e3);
                den0 += w0; den1 += w1; den2 += w2; den3 += w3;
                float2 fa0 = unpackh2(ua[j].x), fa1 = unpackh2(ua[j].y);
                float2 fb0 = unpackh2(ub[j].x), fb1 = unpackh2(ub[j].y);
                float wa = (h1 == 0) ? w0 : w1;
                float wb = (h1 == 0) ? w2 : w3;
                acc0.x += wa * fa0.x; acc0.y += wa * fa0.y; acc0.z += wa * fa1.x; acc0.w += wa * fa1.y;
                acc1.x += wb * fb0.x; acc1.y += wb * fb0.y; acc1.z += wb * fb1.x; acc1.w += wb * fb1.y;
            }
        }
    }
    for (; i < o1; i++) {
        int s0 = g_srcs[i];
        unsigned zu0 = g_zh[s0 * 32 + lane];
        float4 ev0 = g_eg[2 * s0];
        float4 g30 = g_eg[2 * s0 + 1];
        uint2 ua0 = g_fh[s0 * 64 + lane];
        uint2 ub0 = g_fh[s0 * 64 + 32 + lane];
        float2 zv = unpackh2(zu0);
        zmx = fmaxf(zmx, zv.x); zmy = fmaxf(zmy, zv.y);
        gxs0 += g30.x; gxs1 += g30.y; gxs2 += g30.z; gxs3 += g30.w;
        float e0 = ev0.x + er4.x, e1 = ev0.y + er4.y;
        float e2 = ev0.z + er4.z, e3 = ev0.w + er4.w;
        e0 = (e0 > 0.f) ? e0 : 0.2f * e0;
        e1 = (e1 > 0.f) ? e1 : 0.2f * e1;
        e2 = (e2 > 0.f) ? e2 : 0.2f * e2;
        e3 = (e3 > 0.f) ? e3 : 0.2f * e3;
        float w0 = __expf(e0), w1 = __expf(e1);
        float w2 = __expf(e2), w3 = __expf(e3);
        den0 += w0; den1 += w1; den2 += w2; den3 += w3;
        float2 fa0 = unpackh2(ua0.x), fa1 = unpackh2(ua0.y);
        float2 fb0 = unpackh2(ub0.x), fb1 = unpackh2(ub0.y);
        float wa = (h1 == 0) ? w0 : w1;
        float wb = (h1 == 0) ? w2 : w3;
        acc0.x += wa * fa0.x; acc0.y += wa * fa0.y; acc0.z += wa * fa1.x; acc0.w += wa * fa1.y;
        acc1.x += wb * fb0.x; acc1.y += wb * fb0.y; acc1.z += wb * fb1.x; acc1.w += wb * fb1.y;
    }

    // ---- gate ----
    float inv = (deg > 0) ? 1.0f / (float)deg : 0.0f;
    if (deg == 0) { zmx = 0.f; zmy = 0.f; }
    float zr[4];
    int r2 = 2 * lane;
    #pragma unroll
    for (int h = 0; h < 4; h++)
        zr[h] = zmx * sW2[(r2 + 0) * 4 + h] + zmy * sW2[(r2 + 1) * 4 + h];
    #pragma unroll
    for (int dd = 16; dd >= 1; dd >>= 1) {
        #pragma unroll
        for (int h = 0; h < 4; h++) zr[h] += __shfl_xor_sync(0xffffffffu, zr[h], dd);
    }
    float gxs[4] = {gxs0, gxs1, gxs2, gxs3};
    float gx1a[4] = {gx1d.x, gx1d.y, gx1d.z, gx1d.w};
    float gate[4];
    #pragma unroll
    for (int h = 0; h < 4; h++) {
        float p = gx1a[h] + gxs[h] * inv + zr[h] + bg[h];
        gate[h] = 1.f / (1.f + __expf(-p));
    }

    // ---- normalize, bias, gate, head-average, store (fp16) ----
    float4 bga = ((const float4*)bgat)[h1 * 16 + q];
    float4 bgb = ((const float4*)bgat)[(h1 + 2) * 16 + q];
    float4 a0, a1;
    if (deg > 0) {
        float ia = 1.f / ((h1 == 0) ? den0 : den1);
        float ib = 1.f / ((h1 == 0) ? den2 : den3);
        a0.x = acc0.x * ia + bga.x; a0.y = acc0.y * ia + bga.y;
        a0.z = acc0.z * ia + bga.z; a0.w = acc0.w * ia + bga.w;
        a1.x = acc1.x * ib + bgb.x; a1.y = acc1.y * ib + bgb.y;
        a1.z = acc1.z * ib + bgb.z; a1.w = acc1.w * ib + bgb.w;
    } else {
        a0 = bga; a1 = bgb;
    }
    float g0 = (h1 == 0) ? gate[0] : gate[1];
    float g1 = (h1 == 0) ? gate[2] : gate[3];
    float4 pp;
    pp.x = g0 * a0.x + g1 * a1.x;
    pp.y = g0 * a0.y + g1 * a1.y;
    pp.z = g0 * a0.z + g1 * a1.z;
    pp.w = g0 * a0.w + g1 * a1.w;
    pp.x += __shfl_xor_sync(0xffffffffu, pp.x, 16);
    pp.y += __shfl_xor_sync(0xffffffffu, pp.y, 16);
    pp.z += __shfl_xor_sync(0xffffffffu, pp.z, 16);
    pp.w += __shfl_xor_sync(0xffffffffu, pp.w, 16);
    pp.x *= 0.25f; pp.y *= 0.25f; pp.z *= 0.25f; pp.w *= 0.25f;
    if (lane < 16) {
        uint2 u;
        u.x = packh2(pp.x, pp.y);
        u.y = packh2(pp.z, pp.w);
        g_gatedh[d * 16 + lane] = u;
    }
}

// ---------------- merge GEMM: fp16 HMMA + ldmatrix + cp.async double buffer ----------
__global__ void k_merge(const float* __restrict__ bm, float* __restrict__ out) {
    __shared__ unsigned Ah[2][128][12];
    __shared__ unsigned Bk[2][64][12];
    int t = threadIdx.x;
    int rowBase = blockIdx.x * 128;
    int lane = t & 31, wrp = t >> 5;
    int wm = wrp & 3, wn = wrp >> 2;

    float acc[2][4][4];
    #pragma unroll
    for (int mi = 0; mi < 2; mi++)
        #pragma unroll
        for (int ni = 0; ni < 4; ni++)
            #pragma unroll
            for (int q = 0; q < 4; q++) acc[mi][ni][q] = 0.f;

    int arow = t >> 1, ahalf = t & 1;
    int grA = rowBase + arow; if (grA >= NN) grA = NN - 1;
    const uint2* axsrc = &g_xh[grA * 32 + ahalf * 2];
    const uint2* agsrc = &g_gatedh[grA * 16 + ahalf * 2];
    unsigned adst = s2u(&Ah[0][arow][ahalf * 4]);
    bool doB = t < 128;
    int brow = (t >> 1) & 63, bhalf = t & 1;
    const unsigned* bsrc = &g_wmh[brow * 96 + bhalf * 4];
    unsigned bdst = s2u(&Bk[0][brow][bhalf * 4]);

    int lrow = lane & 15, lhalf = lane >> 4;
    unsigned aAddr0 = s2u(&Ah[0][wm * 32 + lrow][lhalf * 4]);
    unsigned aAddr1 = s2u(&Ah[0][wm * 32 + 16 + lrow][lhalf * 4]);
    unsigned bAddr0 = s2u(&Bk[0][wn * 32 + lrow][lhalf * 4]);
    unsigned bAddr1 = s2u(&Bk[0][wn * 32 + 16 + lrow][lhalf * 4]);
    const unsigned ABUF = 128 * 12 * 4, BBUF = 64 * 12 * 4;

    cp16(adst, axsrc);
    if (doB) cp16(bdst, bsrc);
    cp_commit();

    for (int kt = 0; kt < 12; kt++) {
        int cur = kt & 1;
        if (kt < 11) {
            int nxt = cur ^ 1;
            int kn = kt + 1;
            const void* asrcN = (kn < 8) ? (const void*)(axsrc + kn * 4)
                                         : (const void*)(agsrc + (kn - 8) * 4);
            cp16(adst + nxt * ABUF, asrcN);
            if (doB) cp16(bdst + nxt * BBUF, bsrc + kn * 8);
            cp_commit();
            cp_wait1();
        } else {
            cp_wait0();
        }
        __syncthreads();
        unsigned a[2][4], b[2][4];
        ldsm4(a[0][0], a[0][1], a[0][2], a[0][3], aAddr0 + cur * ABUF);
        ldsm4(a[1][0], a[1][1], a[1][2], a[1][3], aAddr1 + cur * ABUF);
        ldsm4(b[0][0], b[0][1], b[0][2], b[0][3], bAddr0 + cur * BBUF);
        ldsm4(b[1][0], b[1][1], b[1][2], b[1][3], bAddr1 + cur * BBUF);
        #pragma unroll
        for (int ni = 0; ni < 4; ni++) {
            unsigned b0 = b[ni >> 1][ni & 1];
            unsigned b1 = b[ni >> 1][(ni & 1) + 2];
            hmma16(acc[0][ni], a[0][0], a[0][1], a[0][2], a[0][3], b0, b1);
            hmma16(acc[1][ni], a[1][0], a[1][1], a[1][2], a[1][3], b0, b1);
        }
        __syncthreads();
    }

    int g = lane >> 2, tig = lane & 3;
    #pragma unroll
    for (int mi = 0; mi < 2; mi++) {
        #pragma unroll
        for (int ni = 0; ni < 4; ni++) {
            int lc = wn * 32 + ni * 8 + tig * 2;
            #pragma unroll
            for (int half = 0; half < 2; half++) {
                int r = rowBase + wm * 32 + mi * 16 + g + half * 8;
                if (r < NN) {
                    out[r * OUT_F + lc]     = acc[mi][ni][half * 2 + 0] + bm[lc];
                    out[r * OUT_F + lc + 1] = acc[mi][ni][half * 2 + 1] + bm[lc + 1];
                }
            }
        }
    }
}

// ---------------- launch ----------------
extern "C" void kernel_launch(void* const* d_in, const int* in_sizes, int n_in,
                              void* d_out, int out_size) {
    const float* x      = (const float*)d_in[0];
    const int*   ei     = (const int*)d_in[1];
    const float* W_gm   = (const float*)d_in[2];
    const float* b_gm   = (const float*)d_in[3];
    const float* W_gate = (const float*)d_in[4];
    const float* b_gate = (const float*)d_in[5];
    const float* W_fc   = (const float*)d_in[6];
    const float* attn_l = (const float*)d_in[7];
    const float* attn_r = (const float*)d_in[8];
    const float* b_gat  = (const float*)d_in[9];
    const float* W_mrg  = (const float*)d_in[10];
    const float* b_mrg  = (const float*)d_in[11];
    float* out = (float*)d_out;

    const int* src = ei;
    const int* dst = ei + EE;

    k_histprep<<<(NN * 32 + 255) / 256, 256>>>(x, W_gm, W_fc, W_mrg, dst);
    k_hist<<<(EE / 4 + 255) / 256, 256>>>(dst);
    k_scan1<<<NB, SCAN_BS>>>();
    k_gemm1<<<(NN + 127) / 128, 256>>>(b_gm);   // index 3: profiled
    k_scan2<<<1, 128>>>();
    k_scan3<<<NB, SCAN_BS>>>();
    k_scatter<<<(EE / 4 + 255) / 256, 256>>>(src, dst);
    k_pre<<<(NN + 7) / 8, 256>>>(x, attn_l, attn_r, W_gate);
    k_agg<<<(NN + 7) / 8, 256>>>(W_gate, b_gate, b_gat);
    k_merge<<<(NN + 127) / 128, 256>>>(b_mrg, out);
}

// round 17
// speedup vs baseline: 1.0879x; 1.0267x over previous
#include <cuda_runtime.h>
#include <cuda_fp16.h>

#define NN   50000
#define EE   800000
#define IN_F 128
#define OUT_F 64
#define MAPF 64
#define NH   4
#define SCAN_BS 512
#define NB ((NN + SCAN_BS - 1) / SCAN_BS)   // 98

// ---------------- scratch (static device globals; no allocation) ----------------
__device__ int   g_count[NN];
__device__ int   g_off[NN + 1];
__device__ int   g_cursor[NN];
__device__ int   g_bsum[NB];
__device__ int   g_bbase[NB];
__device__ int   g_srcs[EE];
__device__ uint2    g_xh[NN * 32];    // x as fp16: 128 halfs/row
__device__ unsigned g_w1h[320 * 64];  // [W_gm | W_fc] K-major fp16
__device__ unsigned g_wmh[64 * 96];   // W_merge K-major fp16
__device__ unsigned g_zh[NN * 32];    // z as fp16
__device__ uint2    g_fh[NN * 64];    // feat as fp16 ([h][64])
__device__ float4 g_eg[NN * 2];       // [2n]=el, [2n+1]=gx3
__device__ float4 g_er4[NN];
__device__ float4 g_gx1[NN];
__device__ uint2  g_gatedh[NN * 16];  // gated as fp16

// ---------------- helpers ----------------
__device__ __forceinline__ void hmma16(float* c, unsigned a0, unsigned a1, unsigned a2,
                                       unsigned a3, unsigned b0, unsigned b1) {
    asm volatile(
        "mma.sync.aligned.m16n8k16.row.col.f32.f16.f16.f32 "
        "{%0,%1,%2,%3},{%4,%5,%6,%7},{%8,%9},{%0,%1,%2,%3};"
        : "+f"(c[0]), "+f"(c[1]), "+f"(c[2]), "+f"(c[3])
        : "r"(a0), "r"(a1), "r"(a2), "r"(a3), "r"(b0), "r"(b1));
}
__device__ __forceinline__ void ldsm4(unsigned& r0, unsigned& r1, unsigned& r2,
                                      unsigned& r3, unsigned saddr) {
    asm volatile("ldmatrix.sync.aligned.m8n8.x4.shared.b16 {%0,%1,%2,%3}, [%4];"
                 : "=r"(r0), "=r"(r1), "=r"(r2), "=r"(r3) : "r"(saddr));
}
__device__ __forceinline__ unsigned s2u(const void* p) {
    return (unsigned)__cvta_generic_to_shared(p);
}
__device__ __forceinline__ void cp16(unsigned dst, const void* src) {
    asm volatile("cp.async.cg.shared.global [%0], [%1], 16;" :: "r"(dst), "l"(src));
}
__device__ __forceinline__ void cp_commit() { asm volatile("cp.async.commit_group;"); }
__device__ __forceinline__ void cp_wait0()  { asm volatile("cp.async.wait_group 0;"); }
__device__ __forceinline__ unsigned packh2(float a, float b) {
    __half2 h = __floats2half2_rn(a, b);
    return *(unsigned*)&h;
}
__device__ __forceinline__ float2 unpackh2(unsigned u) {
    return __half22float2(*(__half2*)&u);
}

// ---------------- fused: zero counts + x->fp16 + weights->fp16 ----------------------
__global__ void k_histprep(const float* __restrict__ x,
                           const float* __restrict__ Wgm, const float* __restrict__ Wfc,
                           const float* __restrict__ Wm, const int* __restrict__ dst) {
    int i = blockIdx.x * blockDim.x + threadIdx.x;
    if (i < NN) g_count[i] = 0;
    if (i < NN * 32) {
        float4 v = ((const float4*)x)[i];
        uint2 u;
        u.x = packh2(v.x, v.y);
        u.y = packh2(v.z, v.w);
        g_xh[i] = u;
    }
    if (i < 320 * 64) {
        int n = i >> 6, j = i & 63;
        int k = 2 * j;
        float a, b;
        if (n < 64) { a = Wgm[k * 64 + n];        b = Wgm[(k + 1) * 64 + n]; }
        else        { a = Wfc[k * 256 + n - 64];  b = Wfc[(k + 1) * 256 + n - 64]; }
        g_w1h[i] = packh2(a, b);
    } else {
        int i2 = i - 320 * 64;
        if (i2 < 64 * 96) {
            int n = i2 / 96, j = i2 % 96;
            int k = 2 * j;
            g_wmh[i2] = packh2(Wm[k * 64 + n], Wm[(k + 1) * 64 + n]);
        }
    }
}

__global__ void k_hist(const int* __restrict__ dst) {
    int e4 = blockIdx.x * blockDim.x + threadIdx.x;
    if (e4 < EE / 4) {
        int4 d = ((const int4*)dst)[e4];
        atomicAdd(&g_count[d.x], 1);
        atomicAdd(&g_count[d.y], 1);
        atomicAdd(&g_count[d.z], 1);
        atomicAdd(&g_count[d.w], 1);
    }
}

__global__ void k_scan1() {
    __shared__ int wsum[16];
    int b = blockIdx.x, t = threadIdx.x, lane = t & 31, w = t >> 5;
    int i = b * SCAN_BS + t;
    int v = (i < NN) ? g_count[i] : 0;
    int xs = v;
    #pragma unroll
    for (int d = 1; d < 32; d <<= 1) {
        int y = __shfl_up_sync(0xffffffffu, xs, d);
        if (lane >= d) xs += y;
    }
    if (lane == 31) wsum[w] = xs;
    __syncthreads();
    if (w == 0) {
        int s = (lane < 16) ? wsum[lane] : 0;
        #pragma unroll
        for (int d = 1; d < 16; d <<= 1) {
            int y = __shfl_up_sync(0xffffffffu, s, d);
            if (lane >= d) s += y;
        }
        if (lane < 16) wsum[lane] = s;
    }
    __syncthreads();
    int base = (w > 0) ? wsum[w - 1] : 0;
    if (i < NN) g_off[i] = base + xs - v;
    if (t == SCAN_BS - 1) g_bsum[b] = wsum[15];
}

__global__ void k_scan2() {
    __shared__ int ws[4];
    int t = threadIdx.x, lane = t & 31, w = t >> 5;
    int v = (t < NB) ? g_bsum[t] : 0;
    int xs = v;
    #pragma unroll
    for (int d = 1; d < 32; d <<= 1) {
        int y = __shfl_up_sync(0xffffffffu, xs, d);
        if (lane >= d) xs += y;
    }
    if (lane == 31) ws[w] = xs;
    __syncthreads();
    if (t == 0) {
        int a = 0;
        #pragma unroll
        for (int k = 0; k < 4; k++) { int tmp = ws[k]; ws[k] = a; a += tmp; }
    }
    __syncthreads();
    if (t < NB) g_bbase[t] = ws[w] + xs - v;
}

__global__ void k_scan3() {
    int b = blockIdx.x, t = threadIdx.x;
    int i = b * SCAN_BS + t;
    if (i < NN) {
        int o = g_off[i] + g_bbase[b];
        g_off[i] = o;
        g_cursor[i] = o;
    }
    if (i == 0) g_off[NN] = EE;
}

__global__ void k_scatter(const int* __restrict__ src, const int* __restrict__ dst) {
    int e4 = blockIdx.x * blockDim.x + threadIdx.x;
    if (e4 < EE / 4) {
        int4 d = ((const int4*)dst)[e4];
        int4 s = ((const int4*)src)[e4];
        g_srcs[atomicAdd(&g_cursor[d.x], 1)] = s.x;
        g_srcs[atomicAdd(&g_cursor[d.y], 1)] = s.y;
        g_srcs[atomicAdd(&g_cursor[d.z], 1)] = s.z;
        g_srcs[atomicAdd(&g_cursor[d.w], 1)] = s.w;
    }
}

// ---------------- GEMM1: A-resident (XOR-swizzled 48KB smem), 5 output tiles ---------
__global__ void k_gemm1(const float* __restrict__ bgm) {
    __shared__ unsigned As[128 * 64];   // 32 KB
    __shared__ unsigned Bs[64 * 64];    // 16 KB
    int t = threadIdx.x;
    int rowBase = blockIdx.x * 128;
    int lane = t & 31, wrp = t >> 5;
    int wm = wrp & 3, wn = wrp >> 2;

    #pragma unroll
    for (int c = 0; c < 8; c++) {
        int ch = t + c * 256;
        int row = ch >> 4, q = ch & 15;
        int gr = rowBase + row; if (gr >= NN) gr = NN - 1;
        cp16(s2u(&As[row * 64 + ((q ^ (row & 7)) << 2)]), &g_xh[gr * 32 + q * 2]);
    }
    #pragma unroll
    for (int c = 0; c < 4; c++) {
        int ch = t + c * 256;
        int row = ch >> 4, q = ch & 15;
        cp16(s2u(&Bs[row * 64 + ((q ^ (row & 7)) << 2)]), &g_w1h[row * 64 + q * 4]);
    }
    cp_commit();
    cp_wait0();
    __syncthreads();

    int lrow = lane & 15, lhalf = lane >> 4;
    int arw0 = wm * 32 + lrow, arw1 = arw0 + 16;
    int brw0 = wn * 32 + lrow, brw1 = brw0 + 16;
    unsigned aB0 = s2u(As) + arw0 * 256;
    unsigned aB1 = s2u(As) + arw1 * 256;
    unsigned bB0 = s2u(Bs) + brw0 * 256;
    unsigned bB1 = s2u(Bs) + brw1 * 256;
    int ax = arw0 & 7, bx = brw0 & 7;
    int g = lane >> 2, tig = lane & 3;

    for (int nt = 0; nt < 5; nt++) {
        float acc[2][4][4];
        #pragma unroll
        for (int mi = 0; mi < 2; mi++)
            #pragma unroll
            for (int ni = 0; ni < 4; ni++)
                #pragma unroll
                for (int q = 0; q < 4; q++) acc[mi][ni][q] = 0.f;

        #pragma unroll
        for (int kt = 0; kt < 8; kt++) {
            int K = kt * 2 + lhalf;
            unsigned a[2][4], b[2][4];
            ldsm4(a[0][0], a[0][1], a[0][2], a[0][3], aB0 + ((K ^ ax) << 4));
            ldsm4(a[1][0], a[1][1], a[1][2], a[1][3], aB1 + ((K ^ ax) << 4));
            ldsm4(b[0][0], b[0][1], b[0][2], b[0][3], bB0 + ((K ^ bx) << 4));
            ldsm4(b[1][0], b[1][1], b[1][2], b[1][3], bB1 + ((K ^ bx) << 4));
            #pragma unroll
            for (int ni = 0; ni < 4; ni++) {
                unsigned b0 = b[ni >> 1][ni & 1];
                unsigned b1 = b[ni >> 1][(ni & 1) + 2];
                hmma16(acc[0][ni], a[0][0], a[0][1], a[0][2], a[0][3], b0, b1);
                hmma16(acc[1][ni], a[1][0], a[1][1], a[1][2], a[1][3], b0, b1);
            }
        }

        #pragma unroll
        for (int mi = 0; mi < 2; mi++) {
            #pragma unroll
            for (int ni = 0; ni < 4; ni++) {
                int lc = wn * 32 + ni * 8 + tig * 2;
                #pragma unroll
                for (int half = 0; half < 2; half++) {
                    int r = rowBase + wm * 32 + mi * 16 + g + half * 8;
                    if (r < NN) {
                        float v0 = acc[mi][ni][half * 2 + 0];
                        float v1 = acc[mi][ni][half * 2 + 1];
                        if (nt == 0) {
                            g_zh[r * 32 + (lc >> 1)] = packh2(v0 + bgm[lc], v1 + bgm[lc + 1]);
                        } else {
                            ((unsigned*)g_fh)[r * 128 + (((nt - 1) * 64 + lc) >> 1)] = packh2(v0, v1);
                        }
                    }
                }
            }
        }
        if (nt < 4) {
            __syncthreads();
            #pragma unroll
            for (int c = 0; c < 4; c++) {
                int ch = t + c * 256;
                int row = ch >> 4, q = ch & 15;
                cp16(s2u(&Bs[row * 64 + ((q ^ (row & 7)) << 2)]),
                     &g_w1h[((nt + 1) * 64 + row) * 64 + q * 4]);
            }
            cp_commit();
            cp_wait0();
            __syncthreads();
        }
    }
}

// ---------------- k_pre: el/er + gx1/gx3 per node (warp per node) ----------------
__global__ void k_pre(const float* __restrict__ x,
                      const float* __restrict__ al, const float* __restrict__ ar,
                      const float* __restrict__ Wg) {
    __shared__ float sW1[IN_F * NH];
    __shared__ float sW3[IN_F * NH];
    for (int i = threadIdx.x; i < IN_F * NH; i += blockDim.x) {
        sW1[i] = Wg[i];
        sW3[i] = Wg[192 * NH + i];
    }
    __syncthreads();
    int w = threadIdx.x >> 5, lane = threadIdx.x & 31;
    int n = blockIdx.x * 8 + w;
    if (n >= NN) return;
    int h1 = lane >> 4, q = lane & 15;

    uint2 ua = g_fh[n * 64 + lane];
    uint2 ub = g_fh[n * 64 + 32 + lane];
    float2 fa0 = unpackh2(ua.x), fa1 = unpackh2(ua.y);
    float2 fb0 = unpackh2(ub.x), fb1 = unpackh2(ub.y);
    const float4* al4 = (const float4*)al;
    const float4* ar4 = (const float4*)ar;
    float4 a0 = al4[h1 * 16 + q], a1 = al4[(h1 + 2) * 16 + q];
    float4 r0 = ar4[h1 * 16 + q], r1 = ar4[(h1 + 2) * 16 + q];
    float el0 = fa0.x * a0.x + fa0.y * a0.y + fa1.x * a0.z + fa1.y * a0.w;
    float el1 = fb0.x * a1.x + fb0.y * a1.y + fb1.x * a1.z + fb1.y * a1.w;
    float er0 = fa0.x * r0.x + fa0.y * r0.y + fa1.x * r0.z + fa1.y * r0.w;
    float er1 = fb0.x * r1.x + fb0.y * r1.y + fb1.x * r1.z + fb1.y * r1.w;

    float4 xv = ((const float4*)x)[n * 32 + lane];
    float gx1[4], gx3[4];
    int r = 4 * lane;
    #pragma unroll
    for (int h = 0; h < 4; h++) {
        gx1[h] = xv.x * sW1[(r + 0) * 4 + h] + xv.y * sW1[(r + 1) * 4 + h]
               + xv.z * sW1[(r + 2) * 4 + h] + xv.w * sW1[(r + 3) * 4 + h];
        gx3[h] = xv.x * sW3[(r + 0) * 4 + h] + xv.y * sW3[(r + 1) * 4 + h]
               + xv.z * sW3[(r + 2) * 4 + h] + xv.w * sW3[(r + 3) * 4 + h];
    }

    #pragma unroll
    for (int d = 8; d >= 1; d >>= 1) {
        el0 += __shfl_down_sync(0xffffffffu, el0, d);
        el1 += __shfl_down_sync(0xffffffffu, el1, d);
        er0 += __shfl_down_sync(0xffffffffu, er0, d);
        er1 += __shfl_down_sync(0xffffffffu, er1, d);
    }
    #pragma unroll
    for (int d = 16; d >= 1; d >>= 1) {
        #pragma unroll
        for (int h = 0; h < 4; h++) {
            gx1[h] += __shfl_xor_sync(0xffffffffu, gx1[h], d);
            gx3[h] += __shfl_xor_sync(0xffffffffu, gx3[h], d);
        }
    }
    float elh1 = __shfl_sync(0xffffffffu, el0, 16);
    float elh3 = __shfl_sync(0xffffffffu, el1, 16);
    float erh1 = __shfl_sync(0xffffffffu, er0, 16);
    float erh3 = __shfl_sync(0xffffffffu, er1, 16);
    if (lane == 0) {
        g_eg[2 * n]     = make_float4(el0, elh1, el1, elh3);
        g_eg[2 * n + 1] = make_float4(gx3[0], gx3[1], gx3[2], gx3[3]);
        g_er4[n]        = make_float4(er0, erh1, er1, erh3);
        g_gx1[n]        = make_float4(gx1[0], gx1[1], gx1[2], gx1[3]);
    }
}

// ---------------- fused single-pass agg (fp16 gated store) ----------------------------
__global__ void k_agg(const float* __restrict__ Wg, const float* __restrict__ bg,
                      const float* __restrict__ bgat) {
    __shared__ float sW2[MAPF * NH];
    for (int i = threadIdx.x; i < MAPF * NH; i += blockDim.x) sW2[i] = Wg[IN_F * NH + i];
    __syncthreads();
    int w = threadIdx.x >> 5, lane = threadIdx.x & 31;
    int d = blockIdx.x * 8 + w;
    if (d >= NN) return;
    int o0 = g_off[d], o1 = g_off[d + 1];
    int deg = o1 - o0;

    float4 er4 = g_er4[d];
    float4 gx1d = g_gx1[d];
    int h1 = lane >> 4, q = lane & 15;

    float zmx = -1e30f, zmy = -1e30f;
    float gxs0 = 0.f, gxs1 = 0.f, gxs2 = 0.f, gxs3 = 0.f;
    float den0 = 0.f, den1 = 0.f, den2 = 0.f, den3 = 0.f;
    float4 acc0 = {0.f, 0.f, 0.f, 0.f}, acc1 = {0.f, 0.f, 0.f, 0.f};

    int i = o0;
    if (deg >= 4) {
        int last = o1 - 1;
        int p0 = g_srcs[i], p1 = g_srcs[i + 1], p2 = g_srcs[i + 2], p3 = g_srcs[i + 3];
        for (; i + 3 < o1; i += 4) {
            int s[4] = {p0, p1, p2, p3};
            unsigned zu[4]; float4 ev[4], g3[4]; uint2 ua[4], ub[4];
            #pragma unroll
            for (int j = 0; j < 4; j++) {
                zu[j] = g_zh[s[j] * 32 + lane];
                ev[j] = g_eg[2 * s[j]];
                g3[j] = g_eg[2 * s[j] + 1];
                ua[j] = g_fh[s[j] * 64 + lane];
                ub[j] = g_fh[s[j] * 64 + 32 + lane];
            }
            int nb = i + 4;
            p0 = g_srcs[min(nb,     last)];
            p1 = g_srcs[min(nb + 1, last)];
            p2 = g_srcs[min(nb + 2, last)];
            p3 = g_srcs[min(nb + 3, last)];
            #pragma unroll
            for (int j = 0; j < 4; j++) {
                float2 zv = unpackh2(zu[j]);
                zmx = fmaxf(zmx, zv.x); zmy = fmaxf(zmy, zv.y);
                gxs0 += g3[j].x; gxs1 += g3[j].y; gxs2 += g3[j].z; gxs3 += g3[j].w;
                float e0 = ev[j].x + er4.x, e1 = ev[j].y + er4.y;
                float e2 = ev[j].z + er4.z, e3 = ev[j].w + er4.w;
                e0 = (e0 > 0.f) ? e0 : 0.2f * e0;
                e1 = (e1 > 0.f) ? e1 : 0.2f * e1;
                e2 = (e2 > 0.f) ? e2 : 0.2f * e2;
                e3 = (e3 > 0.f) ? e3 : 0.2f * e3;
                float w0 = __expf(e0), w1 = __expf(e1);
                float w2 = __expf(e2), w3 = __expf(e3);
                den0 += w0; den1 += w1; den2 += w2; den3 += w3;
                float2 fa0 = unpackh2(ua[j].x), fa1 = unpackh2(ua[j].y);
                float2 fb0 = unpackh2(ub[j].x), fb1 = unpackh2(ub[j].y);
                float wa = (h1 == 0) ? w0 : w1;
                float wb = (h1 == 0) ? w2 : w3;
                acc0.x += wa * fa0.x; acc0.y += wa * fa0.y; acc0.z += wa * fa1.x; acc0.w += wa * fa1.y;
                acc1.x += wb * fb0.x; acc1.y += wb * fb0.y; acc1.z += wb * fb1.x; acc1.w += wb * fb1.y;
            }
        }
    }
    for (; i < o1; i++) {
        int s0 = g_srcs[i];
        unsigned zu0 = g_zh[s0 * 32 + lane];
        float4 ev0 = g_eg[2 * s0];
        float4 g30 = g_eg[2 * s0 + 1];
        uint2 ua0 = g_fh[s0 * 64 + lane];
        uint2 ub0 = g_fh[s0 * 64 + 32 + lane];
        float2 zv = unpackh2(zu0);
        zmx = fmaxf(zmx, zv.x); zmy = fmaxf(zmy, zv.y);
        gxs0 += g30.x; gxs1 += g30.y; gxs2 += g30.z; gxs3 += g30.w;
        float e0 = ev0.x + er4.x, e1 = ev0.y + er4.y;
        float e2 = ev0.z + er4.z, e3 = ev0.w + er4.w;
        e0 = (e0 > 0.f) ? e0 : 0.2f * e0;
        e1 = (e1 > 0.f) ? e1 : 0.2f * e1;
        e2 = (e2 > 0.f) ? e2 : 0.2f * e2;
        e3 = (e3 > 0.f) ? e3 : 0.2f * e3;
        float w0 = __expf(e0), w1 = __expf(e1);
        float w2 = __expf(e2), w3 = __expf(e3);
        den0 += w0; den1 += w1; den2 += w2; den3 += w3;
        float2 fa0 = unpackh2(ua0.x), fa1 = unpackh2(ua0.y);
        float2 fb0 = unpackh2(ub0.x), fb1 = unpackh2(ub0.y);
        float wa = (h1 == 0) ? w0 : w1;
        float wb = (h1 == 0) ? w2 : w3;
        acc0.x += wa * fa0.x; acc0.y += wa * fa0.y; acc0.z += wa * fa1.x; acc0.w += wa * fa1.y;
        acc1.x += wb * fb0.x; acc1.y += wb * fb0.y; acc1.z += wb * fb1.x; acc1.w += wb * fb1.y;
    }

    // ---- gate ----
    float inv = (deg > 0) ? 1.0f / (float)deg : 0.0f;
    if (deg == 0) { zmx = 0.f; zmy = 0.f; }
    float zr[4];
    int r2 = 2 * lane;
    #pragma unroll
    for (int h = 0; h < 4; h++)
        zr[h] = zmx * sW2[(r2 + 0) * 4 + h] + zmy * sW2[(r2 + 1) * 4 + h];
    #pragma unroll
    for (int dd = 16; dd >= 1; dd >>= 1) {
        #pragma unroll
        for (int h = 0; h < 4; h++) zr[h] += __shfl_xor_sync(0xffffffffu, zr[h], dd);
    }
    float gxs[4] = {gxs0, gxs1, gxs2, gxs3};
    float gx1a[4] = {gx1d.x, gx1d.y, gx1d.z, gx1d.w};
    float gate[4];
    #pragma unroll
    for (int h = 0; h < 4; h++) {
        float p = gx1a[h] + gxs[h] * inv + zr[h] + bg[h];
        gate[h] = 1.f / (1.f + __expf(-p));
    }

    // ---- normalize, bias, gate, head-average, store (fp16) ----
    float4 bga = ((const float4*)bgat)[h1 * 16 + q];
    float4 bgb = ((const float4*)bgat)[(h1 + 2) * 16 + q];
    float4 a0, a1;
    if (deg > 0) {
        float ia = 1.f / ((h1 == 0) ? den0 : den1);
        float ib = 1.f / ((h1 == 0) ? den2 : den3);
        a0.x = acc0.x * ia + bga.x; a0.y = acc0.y * ia + bga.y;
        a0.z = acc0.z * ia + bga.z; a0.w = acc0.w * ia + bga.w;
        a1.x = acc1.x * ib + bgb.x; a1.y = acc1.y * ib + bgb.y;
        a1.z = acc1.z * ib + bgb.z; a1.w = acc1.w * ib + bgb.w;
    } else {
        a0 = bga; a1 = bgb;
    }
    float g0 = (h1 == 0) ? gate[0] : gate[1];
    float g1 = (h1 == 0) ? gate[2] : gate[3];
    float4 pp;
    pp.x = g0 * a0.x + g1 * a1.x;
    pp.y = g0 * a0.y + g1 * a1.y;
    pp.z = g0 * a0.z + g1 * a1.z;
    pp.w = g0 * a0.w + g1 * a1.w;
    pp.x += __shfl_xor_sync(0xffffffffu, pp.x, 16);
    pp.y += __shfl_xor_sync(0xffffffffu, pp.y, 16);
    pp.z += __shfl_xor_sync(0xffffffffu, pp.z, 16);
    pp.w += __shfl_xor_sync(0xffffffffu, pp.w, 16);
    pp.x *= 0.25f; pp.y *= 0.25f; pp.z *= 0.25f; pp.w *= 0.25f;
    if (lane < 16) {
        uint2 u;
        u.x = packh2(pp.x, pp.y);
        u.y = packh2(pp.z, pp.w);
        g_gatedh[d * 16 + lane] = u;
    }
}

// ---------------- merge GEMM: two-phase A-resident (48KB static) ----------------------
// Phase 1: x (128x64w, 32KB) + Wm[0:128] (64x64w, 16KB), 8 sync-free k-tiles.
// Phase 2 (same smem): gated (128x32w, 16KB) + Wm[128:192] (64x32w, 8KB), 4 k-tiles.
__global__ void k_merge(const float* __restrict__ bm, float* __restrict__ out) {
    __shared__ unsigned S[128 * 64 + 64 * 64];   // 48 KB
    unsigned* As = S;                 // phase1: 128x64w; phase2: 128x32w
    unsigned* Bs = S + 128 * 64;      // phase1: 64x64w
    unsigned* As2 = S;                // phase2 A at base
    unsigned* Bs2 = S + 128 * 32;     // phase2 B right after (64x32w)
    int t = threadIdx.x;
    int rowBase = blockIdx.x * 128;
    int lane = t & 31, wrp = t >> 5;
    int wm = wrp & 3, wn = wrp >> 2;
    int lrow = lane & 15, lhalf = lane >> 4;
    int arw0 = wm * 32 + lrow, arw1 = arw0 + 16;
    int brw0 = wn * 32 + lrow, brw1 = brw0 + 16;
    int ax = arw0 & 7, bx = brw0 & 7;
    int g = lane >> 2, tig = lane & 3;

    float acc[2][4][4];
    #pragma unroll
    for (int mi = 0; mi < 2; mi++)
        #pragma unroll
        for (int ni = 0; ni < 4; ni++)
            #pragma unroll
            for (int q = 0; q < 4; q++) acc[mi][ni][q] = 0.f;

    // ---- phase 1 load: x rows (16 chunks each) + Wm K 0..127 (16 chunks each) ----
    #pragma unroll
    for (int c = 0; c < 8; c++) {
        int ch = t + c * 256;
        int row = ch >> 4, q = ch & 15;
        int gr = rowBase + row; if (gr >= NN) gr = NN - 1;
        cp16(s2u(&As[row * 64 + ((q ^ (row & 7)) << 2)]), &g_xh[gr * 32 + q * 2]);
    }
    #pragma unroll
    for (int c = 0; c < 4; c++) {
        int ch = t + c * 256;
        int row = ch >> 4, q = ch & 15;
        cp16(s2u(&Bs[row * 64 + ((q ^ (row & 7)) << 2)]), &g_wmh[row * 96 + q * 4]);
    }
    cp_commit();
    cp_wait0();
    __syncthreads();

    {
        unsigned aB0 = s2u(As) + arw0 * 256;
        unsigned aB1 = s2u(As) + arw1 * 256;
        unsigned bB0 = s2u(Bs) + brw0 * 256;
        unsigned bB1 = s2u(Bs) + brw1 * 256;
        #pragma unroll
        for (int kt = 0; kt < 8; kt++) {
            int K = kt * 2 + lhalf;
            unsigned a[2][4], b[2][4];
            ldsm4(a[0][0], a[0][1], a[0][2], a[0][3], aB0 + ((K ^ ax) << 4));
            ldsm4(a[1][0], a[1][1], a[1][2], a[1][3], aB1 + ((K ^ ax) << 4));
            ldsm4(b[0][0], b[0][1], b[0][2], b[0][3], bB0 + ((K ^ bx) << 4));
            ldsm4(b[1][0], b[1][1], b[1][2], b[1][3], bB1 + ((K ^ bx) << 4));
            #pragma unroll
            for (int ni = 0; ni < 4; ni++) {
                unsigned b0 = b[ni >> 1][ni & 1];
                unsigned b1 = b[ni >> 1][(ni & 1) + 2];
                hmma16(acc[0][ni], a[0][0], a[0][1], a[0][2], a[0][3], b0, b1);
                hmma16(acc[1][ni], a[1][0], a[1][1], a[1][2], a[1][3], b0, b1);
            }
        }
    }
    __syncthreads();   // done reading phase-1 smem

    // ---- phase 2 load: gated rows (8 chunks each) + Wm K 128..191 (8 chunks each) ---
    #pragma unroll
    for (int c = 0; c < 4; c++) {
        int ch = t + c * 256;
        int row = ch >> 3, q = ch & 7;
        int gr = rowBase + row; if (gr >= NN) gr = NN - 1;
        cp16(s2u(&As2[row * 32 + ((q ^ (row & 7)) << 2)]), &g_gatedh[gr * 16 + q * 2]);
    }
    #pragma unroll
    for (int c = 0; c < 2; c++) {
        int ch = t + c * 256;
        int row = ch >> 3, q = ch & 7;
        cp16(s2u(&Bs2[row * 32 + ((q ^ (row & 7)) << 2)]), &g_wmh[row * 96 + 64 + q * 4]);
    }
    cp_commit();
    cp_wait0();
    __syncthreads();

    {
        unsigned aB0 = s2u(As2) + arw0 * 128;
        unsigned aB1 = s2u(As2) + arw1 * 128;
        unsigned bB0 = s2u(Bs2) + brw0 * 128;
        unsigned bB1 = s2u(Bs2) + brw1 * 128;
        #pragma unroll
        for (int kt = 0; kt < 4; kt++) {
            int K = kt * 2 + lhalf;
            unsigned a[2][4], b[2][4];
            ldsm4(a[0][0], a[0][1], a[0][2], a[0][3], aB0 + ((K ^ ax) << 4));
            ldsm4(a[1][0], a[1][1], a[1][2], a[1][3], aB1 + ((K ^ ax) << 4));
            ldsm4(b[0][0], b[0][1], b[0][2], b[0][3], bB0 + ((K ^ bx) << 4));
            ldsm4(b[1][0], b[1][1], b[1][2], b[1][3], bB1 + ((K ^ bx) << 4));
            #pragma unroll
            for (int ni = 0; ni < 4; ni++) {
                unsigned b0 = b[ni >> 1][ni & 1];
                unsigned b1 = b[ni >> 1][(ni & 1) + 2];
                hmma16(acc[0][ni], a[0][0], a[0][1], a[0][2], a[0][3], b0, b1);
                hmma16(acc[1][ni], a[1][0], a[1][1], a[1][2], a[1][3], b0, b1);
            }
        }
    }

    #pragma unroll
    for (int mi = 0; mi < 2; mi++) {
        #pragma unroll
        for (int ni = 0; ni < 4; ni++) {
            int lc = wn * 32 + ni * 8 + tig * 2;
            #pragma unroll
            for (int half = 0; half < 2; half++) {
                int r = rowBase + wm * 32 + mi * 16 + g + half * 8;
                if (r < NN) {
                    out[r * OUT_F + lc]     = acc[mi][ni][half * 2 + 0] + bm[lc];
                    out[r * OUT_F + lc + 1] = acc[mi][ni][half * 2 + 1] + bm[lc + 1];
                }
            }
        }
    }
}

// ---------------- launch ----------------
extern "C" void kernel_launch(void* const* d_in, const int* in_sizes, int n_in,
                              void* d_out, int out_size) {
    const float* x      = (const float*)d_in[0];
    const int*   ei     = (const int*)d_in[1];
    const float* W_gm   = (const float*)d_in[2];
    const float* b_gm   = (const float*)d_in[3];
    const float* W_gate = (const float*)d_in[4];
    const float* b_gate = (const float*)d_in[5];
    const float* W_fc   = (const float*)d_in[6];
    const float* attn_l = (const float*)d_in[7];
    const float* attn_r = (const float*)d_in[8];
    const float* b_gat  = (const float*)d_in[9];
    const float* W_mrg  = (const float*)d_in[10];
    const float* b_mrg  = (const float*)d_in[11];
    float* out = (float*)d_out;

    const int* src = ei;
    const int* dst = ei + EE;

    k_histprep<<<(NN * 32 + 255) / 256, 256>>>(x, W_gm, W_fc, W_mrg, dst);
    k_hist<<<(EE / 4 + 255) / 256, 256>>>(dst);
    k_scan1<<<NB, SCAN_BS>>>();
    k_gemm1<<<(NN + 127) / 128, 256>>>(b_gm);   // index 3: profiled
    k_scan2<<<1, 128>>>();
    k_scan3<<<NB, SCAN_BS>>>();
    k_scatter<<<(EE / 4 + 255) / 256, 256>>>(src, dst);
    k_pre<<<(NN + 7) / 8, 256>>>(x, attn_l, attn_r, W_gate);
    k_agg<<<(NN + 7) / 8, 256>>>(W_gate, b_gate, b_gat);
    k_merge<<<(NN + 127) / 128, 256>>>(b_mrg, out);
}